// round 12
// baseline (speedup 1.0000x reference)
#include <cuda_runtime.h>
#include <cuda_bf16.h>
#include <math.h>
#include <cstdint>

#define NN 4096
#define DD 512
#define TT 4096
#define INV_TEMP (1.0f/0.07f)
#define EPSF 1e-8f
#define PD_EPSF 1e-6f
#define MARGINF 0.5f
#define TRIP_W 0.3f
#define NTILE 32                    // 4096/128
#define NTRI  (NTILE*(NTILE+1)/2)   // 528
#define NTRIPB (TT/4)               // 1024 trip CTAs (4 triplets each)

// ---------------- scratch (no dynamic allocation allowed) -----------------
__device__ __nv_bfloat16 g_nembh[NN*DD];  // normalized embeddings, bf16 (4 MB)
__device__ float g_pos[NN];
__device__ float g_tot[NN];
__device__ float g_tpart[NTRIPB];   // per-CTA triplet hinge partials
__device__ int   g_cnt;             // sim completion counter

__device__ __forceinline__ uint32_t smem_u32(const void* p) {
    uint32_t a;
    asm("{ .reg .u64 t; cvta.to.shared.u64 t, %1; cvt.u32.u64 %0, t; }"
        : "=r"(a) : "l"(p));
    return a;
}

#define SW128(o) ((o) ^ (((o) >> 3) & 0x70))

__device__ __forceinline__ void ldsm_x4(uint32_t* r, uint32_t addr) {
    asm volatile("ldmatrix.sync.aligned.m8n8.x4.shared.b16 {%0,%1,%2,%3}, [%4];"
                 : "=r"(r[0]), "=r"(r[1]), "=r"(r[2]), "=r"(r[3]) : "r"(addr));
}
__device__ __forceinline__ void mma16816(float* c, const uint32_t* a,
                                         uint32_t b0, uint32_t b1) {
    asm volatile(
        "mma.sync.aligned.m16n8k16.row.col.f32.bf16.bf16.f32 "
        "{%0,%1,%2,%3}, {%4,%5,%6,%7}, {%8,%9}, {%0,%1,%2,%3};"
        : "+f"(c[0]), "+f"(c[1]), "+f"(c[2]), "+f"(c[3])
        : "r"(a[0]), "r"(a[1]), "r"(a[2]), "r"(a[3]), "r"(b0), "r"(b1));
}

// ---------------------------------------------------------------------------
// Kernel 1 (normtrip): CTAs [0, NN) normalize one row each -> bf16 and zero
// accumulators. CTAs [NN, NN+NTRIPB) compute 4 triplet hinges each (raw emb).
// Both branches depend only on kernel inputs.
// ---------------------------------------------------------------------------
__global__ void normtrip_kernel(const float* __restrict__ emb,
                                const int* __restrict__ trips) {
    int tid  = threadIdx.x;          // 128 threads
    int lane = tid & 31;
    int warp = tid >> 5;

    if (blockIdx.x < NN) {
        // ---------------- norm branch ----------------
        int r = blockIdx.x;
        float4 v = ((const float4*)(emb + (size_t)r * DD))[tid];
        float s = v.x*v.x + v.y*v.y + v.z*v.z + v.w*v.w;
        #pragma unroll
        for (int o = 16; o; o >>= 1) s += __shfl_xor_sync(0xffffffffu, s, o);
        __shared__ float ws[4];
        if (lane == 0) ws[warp] = s;
        __syncthreads();
        float inv = rsqrtf(fmaxf(ws[0] + ws[1] + ws[2] + ws[3], EPSF * EPSF));
        __nv_bfloat162 lo = __floats2bfloat162_rn(v.x * inv, v.y * inv);
        __nv_bfloat162 hi = __floats2bfloat162_rn(v.z * inv, v.w * inv);
        uint2 u;
        u.x = *(uint32_t*)&lo;
        u.y = *(uint32_t*)&hi;
        ((uint2*)(g_nembh + (size_t)r * DD))[tid] = u;
        if (tid == 0) {
            g_pos[r] = 0.0f; g_tot[r] = 0.0f;
            if (r == 0) g_cnt = 0;
        }
    } else {
        // ---------------- trip branch (1 triplet per warp, 4 warps) --------
        __shared__ float s_h[4];
        int tb = blockIdx.x - NN;
        int t = tb * 4 + warp;
        int ia = trips[3*t + 0], ip = trips[3*t + 1], in_ = trips[3*t + 2];
        const float4* pa = (const float4*)(emb + (size_t)ia * DD);
        const float4* pp = (const float4*)(emb + (size_t)ip * DD);
        const float4* pn = (const float4*)(emb + (size_t)in_ * DD);
        float sp = 0.0f, sn = 0.0f;
        #pragma unroll
        for (int w = 0; w < 4; w++) {
            int idx = lane + w * 32;
            float4 a = pa[idx], p = pp[idx], n = pn[idx];
            float d;
            d = a.x - p.x + PD_EPSF; sp = fmaf(d, d, sp);
            d = a.y - p.y + PD_EPSF; sp = fmaf(d, d, sp);
            d = a.z - p.z + PD_EPSF; sp = fmaf(d, d, sp);
            d = a.w - p.w + PD_EPSF; sp = fmaf(d, d, sp);
            d = a.x - n.x + PD_EPSF; sn = fmaf(d, d, sn);
            d = a.y - n.y + PD_EPSF; sn = fmaf(d, d, sn);
            d = a.z - n.z + PD_EPSF; sn = fmaf(d, d, sn);
            d = a.w - n.w + PD_EPSF; sn = fmaf(d, d, sn);
        }
        #pragma unroll
        for (int o = 16; o; o >>= 1) {
            sp += __shfl_xor_sync(0xffffffffu, sp, o);
            sn += __shfl_xor_sync(0xffffffffu, sn, o);
        }
        if (lane == 0)
            s_h[warp] = fmaxf(sqrtf(sp) - sqrtf(sn) + MARGINF, 0.0f);
        __syncthreads();
        if (tid == 0)
            g_tpart[tb] = s_h[0] + s_h[1] + s_h[2] + s_h[3];
    }
}

// ---------------------------------------------------------------------------
// Kernel 2: symmetric bf16 HMMA GEMM, upper-triangle 128x128 tiles (528 CTAs).
// R7-PROVEN single-buffer mainloop (two syncs/chunk) — untouched.
// Last CTA to finish (completion counter) finalizes the loss -> out[0..2].
// ---------------------------------------------------------------------------
#define BK 64
#define NCHUNK (DD / BK)   // 8

__global__ void __launch_bounds__(256) sim_kernel(const int* __restrict__ labels,
                                                  float* __restrict__ out) {
    __shared__ __align__(128) __nv_bfloat16 sA[128 * BK];   // 16 KB
    __shared__ __align__(128) __nv_bfloat16 sB[128 * BK];   // 16 KB
    __shared__ int   s_lcol[128], s_lrow[128];
    __shared__ float s_rpos[128], s_rtot[128], s_cpos[128], s_ctot[128];
    __shared__ int   s_last;

    int tid  = threadIdx.x;
    int lane = tid & 31;
    int wid  = tid >> 5;
    int wm   = wid >> 1;
    int wn   = wid & 1;

    int bi = 0, rem = blockIdx.x;
    while (rem >= NTILE - bi) { rem -= NTILE - bi; bi++; }
    int bj = bi + rem;
    int rb = bi * 128, cb = bj * 128;
    bool diag = (bi == bj);

    if (tid < 128) {
        s_lrow[tid] = labels[rb + tid];
        s_lcol[tid] = labels[cb + tid];
        s_rpos[tid] = 0.0f; s_rtot[tid] = 0.0f;
        s_cpos[tid] = 0.0f; s_ctot[tid] = 0.0f;
    }

    uint32_t baseA = smem_u32(sA), baseB = smem_u32(sB);

    uint32_t a_addr[2];
    #pragma unroll
    for (int mf = 0; mf < 2; mf++) {
        int row = wm * 32 + mf * 16 + (lane & 15);
        a_addr[mf] = baseA + (uint32_t)((row * 128) ^ ((row & 7) << 4))
                   + ((lane >> 4) << 4);
    }
    uint32_t b_addr[4];
    #pragma unroll
    for (int np = 0; np < 4; np++) {
        int row = wn * 64 + np * 16 + (lane & 7) + ((lane >> 4) << 3);
        b_addr[np] = baseB + (uint32_t)((row * 128) ^ ((row & 7) << 4))
                   + (((lane >> 3) & 1) << 4);
    }

    const __nv_bfloat16* gA[4];
    const __nv_bfloat16* gB[4];
    uint32_t stOff[4];
    #pragma unroll
    for (int i = 0; i < 4; i++) {
        int u = tid + 256 * i;
        int row = u >> 3, seg = u & 7;
        gA[i] = g_nembh + (size_t)(rb + row) * DD + seg * 8;
        gB[i] = g_nembh + (size_t)(cb + row) * DD + seg * 8;
        stOff[i] = SW128((uint32_t)(row * 128 + seg * 16));
    }

    float acc[2][8][4];
    #pragma unroll
    for (int mf = 0; mf < 2; mf++)
        #pragma unroll
        for (int nf = 0; nf < 8; nf++)
            #pragma unroll
            for (int k = 0; k < 4; k++) acc[mf][nf][k] = 0.0f;

    uint4 ra[4], rbv[4];
    #pragma unroll
    for (int i = 0; i < 4; i++) { ra[i] = *(const uint4*)gA[i]; rbv[i] = *(const uint4*)gB[i]; }
    #pragma unroll
    for (int i = 0; i < 4; i++) {
        *(uint4*)((char*)sA + stOff[i]) = ra[i];
        *(uint4*)((char*)sB + stOff[i]) = rbv[i];
    }
    __syncthreads();

    #pragma unroll 1
    for (int c = 0; c < NCHUNK; c++) {
        if (c + 1 < NCHUNK) {
            int k0 = (c + 1) * BK;
            #pragma unroll
            for (int i = 0; i < 4; i++) {
                ra[i]  = *(const uint4*)(gA[i] + k0);
                rbv[i] = *(const uint4*)(gB[i] + k0);
            }
        }
        #pragma unroll
        for (int ks = 0; ks < 4; ks++) {
            uint32_t af[2][4], bfr[4][4];
            ldsm_x4(af[0], a_addr[0] + ks * 32);
            ldsm_x4(af[1], a_addr[1] + ks * 32);
            #pragma unroll
            for (int p = 0; p < 4; p++) ldsm_x4(bfr[p], b_addr[p] + ks * 32);
            #pragma unroll
            for (int mf = 0; mf < 2; mf++)
                #pragma unroll
                for (int p = 0; p < 4; p++) {
                    mma16816(acc[mf][2 * p],     af[mf], bfr[p][0], bfr[p][1]);
                    mma16816(acc[mf][2 * p + 1], af[mf], bfr[p][2], bfr[p][3]);
                }
        }
        __syncthreads();
        if (c + 1 < NCHUNK) {
            #pragma unroll
            for (int i = 0; i < 4; i++) {
                *(uint4*)((char*)sA + stOff[i]) = ra[i];
                *(uint4*)((char*)sB + stOff[i]) = rbv[i];
            }
            __syncthreads();
        }
    }

    // ---- epilogue ----
    const float EXP_DIAG = __expf(INV_TEMP);
    int quad = lane >> 2, qid = lane & 3;
    int lrv[2][2];

    #pragma unroll
    for (int mf = 0; mf < 2; mf++) {
        #pragma unroll
        for (int h = 0; h < 2; h++) {
            int R  = wm * 32 + mf * 16 + quad + 8 * h;
            int lr = s_lrow[R];
            lrv[mf][h] = lr;
            float p = 0.0f, t = 0.0f;
            #pragma unroll
            for (int nf = 0; nf < 8; nf++) {
                #pragma unroll
                for (int j = 0; j < 2; j++) {
                    int cidx = wn * 64 + nf * 8 + 2 * qid + j;
                    float e = __expf(acc[mf][nf][2 * h + j] * INV_TEMP);
                    if (diag && cidx == R) {
                        acc[mf][nf][2 * h + j] = 0.0f;
                        t += EXP_DIAG;
                    } else {
                        acc[mf][nf][2 * h + j] = e;
                        t += e;
                        if (s_lcol[cidx] == lr) p += e;
                    }
                }
            }
            p += __shfl_xor_sync(0xffffffffu, p, 1);
            p += __shfl_xor_sync(0xffffffffu, p, 2);
            t += __shfl_xor_sync(0xffffffffu, t, 1);
            t += __shfl_xor_sync(0xffffffffu, t, 2);
            if (qid == 0) {
                atomicAdd(&s_rpos[R], p);
                atomicAdd(&s_rtot[R], t);
            }
        }
    }

    if (!diag) {
        #pragma unroll
        for (int nf = 0; nf < 8; nf++) {
            #pragma unroll
            for (int j = 0; j < 2; j++) {
                int cidx = wn * 64 + nf * 8 + 2 * qid + j;
                int lc = s_lcol[cidx];
                float cp = 0.0f, ct = 0.0f;
                #pragma unroll
                for (int mf = 0; mf < 2; mf++)
                    #pragma unroll
                    for (int h = 0; h < 2; h++) {
                        float e = acc[mf][nf][2 * h + j];
                        ct += e;
                        if (lrv[mf][h] == lc) cp += e;
                    }
                cp += __shfl_xor_sync(0xffffffffu, cp, 4);
                cp += __shfl_xor_sync(0xffffffffu, cp, 8);
                cp += __shfl_xor_sync(0xffffffffu, cp, 16);
                ct += __shfl_xor_sync(0xffffffffu, ct, 4);
                ct += __shfl_xor_sync(0xffffffffu, ct, 8);
                ct += __shfl_xor_sync(0xffffffffu, ct, 16);
                if (quad == 0) {
                    atomicAdd(&s_cpos[cidx], cp);
                    atomicAdd(&s_ctot[cidx], ct);
                }
            }
        }
    }

    __syncthreads();
    if (tid < 128) {
        atomicAdd(&g_pos[rb + tid], s_rpos[tid]);
        atomicAdd(&g_tot[rb + tid], s_rtot[tid]);
    } else if (!diag) {
        int t2 = tid - 128;
        atomicAdd(&g_pos[cb + t2], s_cpos[t2]);
        atomicAdd(&g_tot[cb + t2], s_ctot[t2]);
    }

    // ---- completion-counter finalize (last CTA only) ----
    __syncthreads();
    __threadfence();
    if (tid == 0)
        s_last = (atomicAdd(&g_cnt, 1) == NTRI - 1) ? 1 : 0;
    __syncthreads();
    if (s_last) {
        __threadfence();
        float l = 0.0f, c = 0.0f, ts = 0.0f;
        #pragma unroll
        for (int k = 0; k < NN / 256; k++) {       // 16 independent rows/thread
            int r = tid + k * 256;
            float p = __ldcg(&g_pos[r]);
            float q = __ldcg(&g_tot[r]);
            if (p > 0.0f) {
                l += -__logf(p / (q + EPSF) + EPSF);
                c += 1.0f;
            }
        }
        #pragma unroll
        for (int k = 0; k < NTRIPB / 256; k++)
            ts += g_tpart[tid + k * 256];          // written pre-sim (kernel order)

        #pragma unroll
        for (int o = 16; o; o >>= 1) {
            l  += __shfl_xor_sync(0xffffffffu, l, o);
            c  += __shfl_xor_sync(0xffffffffu, c, o);
            ts += __shfl_xor_sync(0xffffffffu, ts, o);
        }
        if (lane == 0) { s_rpos[wid] = l; s_rtot[wid] = c; s_cpos[wid] = ts; }
        __syncthreads();
        if (tid == 0) {
            float L = s_rpos[0]+s_rpos[1]+s_rpos[2]+s_rpos[3]
                    + s_rpos[4]+s_rpos[5]+s_rpos[6]+s_rpos[7];
            float C = s_rtot[0]+s_rtot[1]+s_rtot[2]+s_rtot[3]
                    + s_rtot[4]+s_rtot[5]+s_rtot[6]+s_rtot[7];
            float S = s_cpos[0]+s_cpos[1]+s_cpos[2]+s_cpos[3]
                    + s_cpos[4]+s_cpos[5]+s_cpos[6]+s_cpos[7];
            float cont = (C > 0.0f) ? (L / C) : 0.0f;
            float trip = S / (float)TT;
            out[0] = cont + TRIP_W * trip;
            out[1] = cont;
            out[2] = trip;
        }
    }
}

// ---------------------------------------------------------------------------
extern "C" void kernel_launch(void* const* d_in, const int* in_sizes, int n_in,
                              void* d_out, int out_size) {
    (void)in_sizes; (void)n_in; (void)out_size;
    const float* emb    = (const float*)d_in[0];
    const int*   labels = (const int*)d_in[1];
    const int*   trips  = (const int*)d_in[2];
    float*       out    = (float*)d_out;

    normtrip_kernel<<<NN + NTRIPB, 128>>>(emb, trips);
    sim_kernel<<<NTRI, 256>>>(labels, out);
}

// round 17
// speedup vs baseline: 1.1463x; 1.1463x over previous
#include <cuda_runtime.h>
#include <cuda_bf16.h>
#include <math.h>
#include <cstdint>

#define NN 4096
#define DD 512
#define TT 4096
#define INV_TEMP (1.0f/0.07f)
#define EPSF 1e-8f
#define PD_EPSF 1e-6f
#define MARGINF 0.5f
#define TRIP_W 0.3f
#define NTILE 32                    // 4096/128
#define NTRI  (NTILE*(NTILE+1)/2)   // 528
#define NTRIPB (TT/4)               // 1024 trip CTAs (4 triplets each)

// ---------------- scratch (no dynamic allocation allowed) -----------------
__device__ __nv_bfloat16 g_nembh[NN*DD];  // normalized embeddings, bf16 (4 MB)
__device__ float g_pos[NN];
__device__ float g_tot[NN];
__device__ float g_tpart[NTRIPB];   // per-CTA triplet hinge partials
__device__ float g_fin[4];          // [0]=loss sum, [1]=valid cnt, [2]=trip sum

__device__ __forceinline__ uint32_t smem_u32(const void* p) {
    uint32_t a;
    asm("{ .reg .u64 t; cvta.to.shared.u64 t, %1; cvt.u32.u64 %0, t; }"
        : "=r"(a) : "l"(p));
    return a;
}

#define SW128(o) ((o) ^ (((o) >> 3) & 0x70))

__device__ __forceinline__ void ldsm_x4(uint32_t* r, uint32_t addr) {
    asm volatile("ldmatrix.sync.aligned.m8n8.x4.shared.b16 {%0,%1,%2,%3}, [%4];"
                 : "=r"(r[0]), "=r"(r[1]), "=r"(r[2]), "=r"(r[3]) : "r"(addr));
}
__device__ __forceinline__ void mma16816(float* c, const uint32_t* a,
                                         uint32_t b0, uint32_t b1) {
    asm volatile(
        "mma.sync.aligned.m16n8k16.row.col.f32.bf16.bf16.f32 "
        "{%0,%1,%2,%3}, {%4,%5,%6,%7}, {%8,%9}, {%0,%1,%2,%3};"
        : "+f"(c[0]), "+f"(c[1]), "+f"(c[2]), "+f"(c[3])
        : "r"(a[0]), "r"(a[1]), "r"(a[2]), "r"(a[3]), "r"(b0), "r"(b1));
}

// ---------------------------------------------------------------------------
// Kernel 1 (normtrip): CTAs [0, NN) normalize one row each -> bf16 and zero
// accumulators (incl. g_fin). CTAs [NN, NN+NTRIPB) compute 4 triplet hinges
// each from raw embeddings. Both branches depend only on kernel inputs.
// (R12-proven: ~6.7us vs 12us serial.)
// ---------------------------------------------------------------------------
__global__ void normtrip_kernel(const float* __restrict__ emb,
                                const int* __restrict__ trips) {
    int tid  = threadIdx.x;          // 128 threads
    int lane = tid & 31;
    int warp = tid >> 5;

    if (blockIdx.x < NN) {
        // ---------------- norm branch ----------------
        int r = blockIdx.x;
        float4 v = ((const float4*)(emb + (size_t)r * DD))[tid];
        float s = v.x*v.x + v.y*v.y + v.z*v.z + v.w*v.w;
        #pragma unroll
        for (int o = 16; o; o >>= 1) s += __shfl_xor_sync(0xffffffffu, s, o);
        __shared__ float ws[4];
        if (lane == 0) ws[warp] = s;
        __syncthreads();
        float inv = rsqrtf(fmaxf(ws[0] + ws[1] + ws[2] + ws[3], EPSF * EPSF));
        __nv_bfloat162 lo = __floats2bfloat162_rn(v.x * inv, v.y * inv);
        __nv_bfloat162 hi = __floats2bfloat162_rn(v.z * inv, v.w * inv);
        uint2 u;
        u.x = *(uint32_t*)&lo;
        u.y = *(uint32_t*)&hi;
        ((uint2*)(g_nembh + (size_t)r * DD))[tid] = u;
        if (tid == 0) {
            g_pos[r] = 0.0f; g_tot[r] = 0.0f;
            if (r == 0) { g_fin[0] = 0.f; g_fin[1] = 0.f; g_fin[2] = 0.f; g_fin[3] = 0.f; }
        }
    } else {
        // ---------------- trip branch (1 triplet per warp, 4 warps) --------
        __shared__ float s_h[4];
        int tb = blockIdx.x - NN;
        int t = tb * 4 + warp;
        int ia = trips[3*t + 0], ip = trips[3*t + 1], in_ = trips[3*t + 2];
        const float4* pa = (const float4*)(emb + (size_t)ia * DD);
        const float4* pp = (const float4*)(emb + (size_t)ip * DD);
        const float4* pn = (const float4*)(emb + (size_t)in_ * DD);
        float sp = 0.0f, sn = 0.0f;
        #pragma unroll
        for (int w = 0; w < 4; w++) {
            int idx = lane + w * 32;
            float4 a = pa[idx], p = pp[idx], n = pn[idx];
            float d;
            d = a.x - p.x + PD_EPSF; sp = fmaf(d, d, sp);
            d = a.y - p.y + PD_EPSF; sp = fmaf(d, d, sp);
            d = a.z - p.z + PD_EPSF; sp = fmaf(d, d, sp);
            d = a.w - p.w + PD_EPSF; sp = fmaf(d, d, sp);
            d = a.x - n.x + PD_EPSF; sn = fmaf(d, d, sn);
            d = a.y - n.y + PD_EPSF; sn = fmaf(d, d, sn);
            d = a.z - n.z + PD_EPSF; sn = fmaf(d, d, sn);
            d = a.w - n.w + PD_EPSF; sn = fmaf(d, d, sn);
        }
        #pragma unroll
        for (int o = 16; o; o >>= 1) {
            sp += __shfl_xor_sync(0xffffffffu, sp, o);
            sn += __shfl_xor_sync(0xffffffffu, sn, o);
        }
        if (lane == 0)
            s_h[warp] = fmaxf(sqrtf(sp) - sqrtf(sn) + MARGINF, 0.0f);
        __syncthreads();
        if (tid == 0)
            g_tpart[tb] = s_h[0] + s_h[1] + s_h[2] + s_h[3];
    }
}

// ---------------------------------------------------------------------------
// Kernel 2: symmetric bf16 HMMA GEMM, upper-triangle 128x128 tiles (528 CTAs).
// R7-PROVEN structure EXACTLY — no fence, no finalize tail.
// ---------------------------------------------------------------------------
#define BK 64
#define NCHUNK (DD / BK)   // 8

__global__ void __launch_bounds__(256, 2) sim_kernel(const int* __restrict__ labels) {
    __shared__ __align__(128) __nv_bfloat16 sA[128 * BK];   // 16 KB
    __shared__ __align__(128) __nv_bfloat16 sB[128 * BK];   // 16 KB
    __shared__ int   s_lcol[128], s_lrow[128];
    __shared__ float s_rpos[128], s_rtot[128], s_cpos[128], s_ctot[128];

    int tid  = threadIdx.x;
    int lane = tid & 31;
    int wid  = tid >> 5;
    int wm   = wid >> 1;
    int wn   = wid & 1;

    int bi = 0, rem = blockIdx.x;
    while (rem >= NTILE - bi) { rem -= NTILE - bi; bi++; }
    int bj = bi + rem;
    int rb = bi * 128, cb = bj * 128;
    bool diag = (bi == bj);

    if (tid < 128) {
        s_lrow[tid] = labels[rb + tid];
        s_lcol[tid] = labels[cb + tid];
        s_rpos[tid] = 0.0f; s_rtot[tid] = 0.0f;
        s_cpos[tid] = 0.0f; s_ctot[tid] = 0.0f;
    }

    uint32_t baseA = smem_u32(sA), baseB = smem_u32(sB);

    uint32_t a_addr[2];
    #pragma unroll
    for (int mf = 0; mf < 2; mf++) {
        int row = wm * 32 + mf * 16 + (lane & 15);
        a_addr[mf] = baseA + (uint32_t)((row * 128) ^ ((row & 7) << 4))
                   + ((lane >> 4) << 4);
    }
    uint32_t b_addr[4];
    #pragma unroll
    for (int np = 0; np < 4; np++) {
        int row = wn * 64 + np * 16 + (lane & 7) + ((lane >> 4) << 3);
        b_addr[np] = baseB + (uint32_t)((row * 128) ^ ((row & 7) << 4))
                   + (((lane >> 3) & 1) << 4);
    }

    const __nv_bfloat16* gA[4];
    const __nv_bfloat16* gB[4];
    uint32_t stOff[4];
    #pragma unroll
    for (int i = 0; i < 4; i++) {
        int u = tid + 256 * i;
        int row = u >> 3, seg = u & 7;
        gA[i] = g_nembh + (size_t)(rb + row) * DD + seg * 8;
        gB[i] = g_nembh + (size_t)(cb + row) * DD + seg * 8;
        stOff[i] = SW128((uint32_t)(row * 128 + seg * 16));
    }

    float acc[2][8][4];
    #pragma unroll
    for (int mf = 0; mf < 2; mf++)
        #pragma unroll
        for (int nf = 0; nf < 8; nf++)
            #pragma unroll
            for (int k = 0; k < 4; k++) acc[mf][nf][k] = 0.0f;

    uint4 ra[4], rbv[4];
    #pragma unroll
    for (int i = 0; i < 4; i++) { ra[i] = *(const uint4*)gA[i]; rbv[i] = *(const uint4*)gB[i]; }
    #pragma unroll
    for (int i = 0; i < 4; i++) {
        *(uint4*)((char*)sA + stOff[i]) = ra[i];
        *(uint4*)((char*)sB + stOff[i]) = rbv[i];
    }
    __syncthreads();

    #pragma unroll 1
    for (int c = 0; c < NCHUNK; c++) {
        if (c + 1 < NCHUNK) {
            int k0 = (c + 1) * BK;
            #pragma unroll
            for (int i = 0; i < 4; i++) {
                ra[i]  = *(const uint4*)(gA[i] + k0);
                rbv[i] = *(const uint4*)(gB[i] + k0);
            }
        }
        #pragma unroll
        for (int ks = 0; ks < 4; ks++) {
            uint32_t af[2][4], bfr[4][4];
            ldsm_x4(af[0], a_addr[0] + ks * 32);
            ldsm_x4(af[1], a_addr[1] + ks * 32);
            #pragma unroll
            for (int p = 0; p < 4; p++) ldsm_x4(bfr[p], b_addr[p] + ks * 32);
            #pragma unroll
            for (int mf = 0; mf < 2; mf++)
                #pragma unroll
                for (int p = 0; p < 4; p++) {
                    mma16816(acc[mf][2 * p],     af[mf], bfr[p][0], bfr[p][1]);
                    mma16816(acc[mf][2 * p + 1], af[mf], bfr[p][2], bfr[p][3]);
                }
        }
        __syncthreads();
        if (c + 1 < NCHUNK) {
            #pragma unroll
            for (int i = 0; i < 4; i++) {
                *(uint4*)((char*)sA + stOff[i]) = ra[i];
                *(uint4*)((char*)sB + stOff[i]) = rbv[i];
            }
            __syncthreads();
        }
    }

    // ---- epilogue ----
    const float EXP_DIAG = __expf(INV_TEMP);
    int quad = lane >> 2, qid = lane & 3;
    int lrv[2][2];

    #pragma unroll
    for (int mf = 0; mf < 2; mf++) {
        #pragma unroll
        for (int h = 0; h < 2; h++) {
            int R  = wm * 32 + mf * 16 + quad + 8 * h;
            int lr = s_lrow[R];
            lrv[mf][h] = lr;
            float p = 0.0f, t = 0.0f;
            #pragma unroll
            for (int nf = 0; nf < 8; nf++) {
                #pragma unroll
                for (int j = 0; j < 2; j++) {
                    int cidx = wn * 64 + nf * 8 + 2 * qid + j;
                    float e = __expf(acc[mf][nf][2 * h + j] * INV_TEMP);
                    if (diag && cidx == R) {
                        acc[mf][nf][2 * h + j] = 0.0f;
                        t += EXP_DIAG;
                    } else {
                        acc[mf][nf][2 * h + j] = e;
                        t += e;
                        if (s_lcol[cidx] == lr) p += e;
                    }
                }
            }
            p += __shfl_xor_sync(0xffffffffu, p, 1);
            p += __shfl_xor_sync(0xffffffffu, p, 2);
            t += __shfl_xor_sync(0xffffffffu, t, 1);
            t += __shfl_xor_sync(0xffffffffu, t, 2);
            if (qid == 0) {
                atomicAdd(&s_rpos[R], p);
                atomicAdd(&s_rtot[R], t);
            }
        }
    }

    if (!diag) {
        #pragma unroll
        for (int nf = 0; nf < 8; nf++) {
            #pragma unroll
            for (int j = 0; j < 2; j++) {
                int cidx = wn * 64 + nf * 8 + 2 * qid + j;
                int lc = s_lcol[cidx];
                float cp = 0.0f, ct = 0.0f;
                #pragma unroll
                for (int mf = 0; mf < 2; mf++)
                    #pragma unroll
                    for (int h = 0; h < 2; h++) {
                        float e = acc[mf][nf][2 * h + j];
                        ct += e;
                        if (lrv[mf][h] == lc) cp += e;
                    }
                cp += __shfl_xor_sync(0xffffffffu, cp, 4);
                cp += __shfl_xor_sync(0xffffffffu, cp, 8);
                cp += __shfl_xor_sync(0xffffffffu, cp, 16);
                ct += __shfl_xor_sync(0xffffffffu, ct, 4);
                ct += __shfl_xor_sync(0xffffffffu, ct, 8);
                ct += __shfl_xor_sync(0xffffffffu, ct, 16);
                if (quad == 0) {
                    atomicAdd(&s_cpos[cidx], cp);
                    atomicAdd(&s_ctot[cidx], ct);
                }
            }
        }
    }

    __syncthreads();
    if (tid < 128) {
        atomicAdd(&g_pos[rb + tid], s_rpos[tid]);
        atomicAdd(&g_tot[rb + tid], s_rtot[tid]);
    } else if (!diag) {
        int t2 = tid - 128;
        atomicAdd(&g_pos[cb + t2], s_cpos[t2]);
        atomicAdd(&g_tot[cb + t2], s_ctot[t2]);
    }
}

// ---------------------------------------------------------------------------
// Kernel 3: per-row contrastive loss + trip partial reduce into g_fin.
// 16 blocks x 256 threads (one row per thread; first 1024 threads also
// pick up one g_tpart entry each).
// ---------------------------------------------------------------------------
__global__ void fin1_kernel() {
    int gid = blockIdx.x * 256 + threadIdx.x;
    float p = g_pos[gid], q = g_tot[gid];
    float l = 0.0f, c = 0.0f, ts = 0.0f;
    if (p > 0.0f) {
        l = -__logf(p / (q + EPSF) + EPSF);
        c = 1.0f;
    }
    if (gid < NTRIPB) ts = g_tpart[gid];
    #pragma unroll
    for (int o = 16; o; o >>= 1) {
        l  += __shfl_xor_sync(0xffffffffu, l, o);
        c  += __shfl_xor_sync(0xffffffffu, c, o);
        ts += __shfl_xor_sync(0xffffffffu, ts, o);
    }
    __shared__ float sl[8], sc[8], st[8];
    int warp = threadIdx.x >> 5, lane = threadIdx.x & 31;
    if (lane == 0) { sl[warp] = l; sc[warp] = c; st[warp] = ts; }
    __syncthreads();
    if (threadIdx.x == 0) {
        float L = sl[0]+sl[1]+sl[2]+sl[3]+sl[4]+sl[5]+sl[6]+sl[7];
        float C = sc[0]+sc[1]+sc[2]+sc[3]+sc[4]+sc[5]+sc[6]+sc[7];
        float S = st[0]+st[1]+st[2]+st[3]+st[4]+st[5]+st[6]+st[7];
        atomicAdd(&g_fin[0], L);
        atomicAdd(&g_fin[1], C);
        atomicAdd(&g_fin[2], S);
    }
}

// ---------------------------------------------------------------------------
// Kernel 4: finalize (1 thread).
// ---------------------------------------------------------------------------
__global__ void fin2_kernel(float* __restrict__ out) {
    float cont = (g_fin[1] > 0.0f) ? (g_fin[0] / g_fin[1]) : 0.0f;
    float trip = g_fin[2] / (float)TT;
    out[0] = cont + TRIP_W * trip;
    out[1] = cont;
    out[2] = trip;
}

// ---------------------------------------------------------------------------
extern "C" void kernel_launch(void* const* d_in, const int* in_sizes, int n_in,
                              void* d_out, int out_size) {
    (void)in_sizes; (void)n_in; (void)out_size;
    const float* emb    = (const float*)d_in[0];
    const int*   labels = (const int*)d_in[1];
    const int*   trips  = (const int*)d_in[2];
    float*       out    = (float*)d_out;

    normtrip_kernel<<<NN + NTRIPB, 128>>>(emb, trips);
    sim_kernel<<<NTRI, 256>>>(labels);
    fin1_kernel<<<16, 256>>>();
    fin2_kernel<<<1, 1>>>(out);
}